// round 14
// baseline (speedup 1.0000x reference)
#include <cuda_runtime.h>
#include <math.h>
#include <stdint.h>

// Problem constants
#define BB   8
#define TT   512
#define DD   128
#define DLL  16
#define KK   8
#define HTH  32
#define NROWS (BB*TT)   // 4096
#define EPS2 0.0001f

// gelu Taylor: gelu(x) = 0.5x + C0 x^2 + C1 x^4 (|x| small)
#define C0g  0.3989422804014327f
#define C1g  (-0.06649038006690545f)

// Phi LUT: 2048 entries over dl2 in [0,16), step 1/128
#define LUTN   2048
#define LUTSCL 128.0f

// Scratch
__device__ __align__(16) float    g_l[2][NROWS*DLL];   // l vectors (tf32-rounded)
__device__ __align__(16) float    g_PQ[2][NROWS*HTH];  // theta vectors (tf32-rounded)
__device__ __align__(16) unsigned g_hb[2][NROWS*64];   // h rows packed bf16x2
__device__ float  g_hn[2][NROWS];
__device__ float  g_ln[2][NROWS];
__device__ float  g_c[2][NROWS];
__device__ __align__(16) float2 g_lut[LUTN];

// ---------------------------------------------------------------------------
// helpers
// ---------------------------------------------------------------------------
__device__ __forceinline__ float tf32r(float x) {
    unsigned u;
    asm("cvt.rna.tf32.f32 %0, %1;" : "=r"(u) : "f"(x));
    return __uint_as_float(u);
}

__device__ __forceinline__ float bf16r(float x) {
    unsigned p;
    asm("cvt.rn.bf16x2.f32 %0, %1, %2;" : "=r"(p) : "f"(x), "f"(x));
    return __uint_as_float(p << 16);
}

__device__ __forceinline__ unsigned bf16pack(float lo, float hi) {
    unsigned p;
    asm("cvt.rn.bf16x2.f32 %0, %1, %2;" : "=r"(p) : "f"(hi), "f"(lo));
    return p;
}

// m16n8k8 tf32 MMA, fp32 accumulate
__device__ __forceinline__ void mma8(float* d, const unsigned* a, const unsigned* b) {
    asm volatile(
        "mma.sync.aligned.m16n8k8.row.col.f32.tf32.tf32.f32 "
        "{%0,%1,%2,%3},{%4,%5,%6,%7},{%8,%9},{%0,%1,%2,%3};"
        : "+f"(d[0]), "+f"(d[1]), "+f"(d[2]), "+f"(d[3])
        : "r"(a[0]), "r"(a[1]), "r"(a[2]), "r"(a[3]), "r"(b[0]), "r"(b[1]));
}

// m16n8k16 bf16 MMA, fp32 accumulate
__device__ __forceinline__ void mma16(float* d, const unsigned* a, const unsigned* b) {
    asm volatile(
        "mma.sync.aligned.m16n8k16.row.col.f32.bf16.bf16.f32 "
        "{%0,%1,%2,%3},{%4,%5,%6,%7},{%8,%9},{%0,%1,%2,%3};"
        : "+f"(d[0]), "+f"(d[1]), "+f"(d[2]), "+f"(d[3])
        : "r"(a[0]), "r"(a[1]), "r"(a[2]), "r"(a[3]), "r"(b[0]), "r"(b[1]));
}

__device__ __forceinline__ unsigned ldsu(const float* p) {
    return __float_as_uint(*p);
}

__device__ __forceinline__ unsigned smem_u32(const void* p) {
    unsigned a;
    asm("{ .reg .u64 t; cvta.to.shared.u64 t, %1; cvt.u32.u64 %0, t; }"
        : "=r"(a) : "l"(p));
    return a;
}

#define CP_ASYNC16(dst_u32, src) \
    asm volatile("cp.async.ca.shared.global [%0], [%1], 16;" \
                 :: "r"(dst_u32), "l"(src) : "memory")

__device__ __forceinline__ float gelu_exact(float x) {
    return 0.5f * x * (1.0f + erff(x * 0.7071067811865475f));
}

// ---------------------------------------------------------------------------
// prep: grid (256, 3), block 128. 16 rows per block (sides 0/1), LUT side 2.
// ---------------------------------------------------------------------------
#define P_SROW 0                       // 16 x 132
#define P_SWT  (P_SROW + 16*132)       // 24 x 132 (transposed weights)
#define P_SL   (P_SWT  + 24*132)       // 16 x 20
#define P_STH  (P_SL   + 16*20)        // 16 x 12
#define P_SCW  (P_STH  + 16*12)        // 8 x 32
#define PREP_SMEM ((P_SCW + 256) * 4)

__global__ __launch_bounds__(128)
void prep_kernel(const float* __restrict__ h,
                 const float* __restrict__ hsrc,
                 const float* __restrict__ W_l,
                 const float* __restrict__ W_theta,
                 const float* __restrict__ wq,
                 const float* __restrict__ ws,
                 const float* __restrict__ wd,
                 const float* __restrict__ b1,
                 const float* __restrict__ w2_w,
                 const float* __restrict__ phi1_w,
                 const float* __restrict__ phi1_b,
                 const float* __restrict__ phi2_w,
                 const float* __restrict__ phi2_b)
{
    int side = blockIdx.y;
    int tid  = threadIdx.x;

    if (side == 2) {
        // LUT: 256 blocks x 4 warps x 2 entries = 2048
        int wid = tid >> 5, lane = tid & 31;
        float w = phi1_w[lane], b = phi1_b[lane], v = phi2_w[lane];
        float ph2b = phi2_b[0];
        #pragma unroll
        for (int sub = 0; sub < 2; sub++) {
            int e = blockIdx.x * 8 + wid * 2 + sub;
            float x0 = (float)e       * (1.0f / LUTSCL);
            float x1 = (float)(e + 1) * (1.0f / LUTSCL);
            float s0 = gelu_exact(fmaf(x0, w, b)) * v;
            float s1 = gelu_exact(fmaf(x1, w, b)) * v;
            #pragma unroll
            for (int o = 16; o > 0; o >>= 1) {
                s0 += __shfl_xor_sync(0xffffffffu, s0, o);
                s1 += __shfl_xor_sync(0xffffffffu, s1, o);
            }
            if (lane == 0) {
                float a0 = s0 + ph2b, a1 = s1 + ph2b;
                float c0 = fmaxf(a0, 0.f) + log1pf(expf(-fabsf(a0)));
                float c1 = fmaxf(a1, 0.f) + log1pf(expf(-fabsf(a1)));
                float p0 = expf(-c0 * x0);
                float p1 = expf(-c1 * x1);
                g_lut[e] = make_float2(p0, p1 - p0);
            }
        }
        return;
    }

    extern __shared__ float ps[];
    float* SROW = ps + P_SROW;
    float* SWT  = ps + P_SWT;
    float* SL   = ps + P_SL;
    float* STH  = ps + P_STH;
    float* SCW  = ps + P_SCW;

    int r0 = blockIdx.x * 16;
    const float* src = (side == 0) ? h : hsrc;

    // ---- stage ----
    {
        const float4* sv = (const float4*)(src + (size_t)r0 * DD);
        #pragma unroll
        for (int i = 0; i < 4; i++) {
            int idx = tid + i * 128;        // < 512 f4
            int r = idx >> 5, c4 = idx & 31;
            *(float4*)(SROW + r * 132 + c4 * 4) = sv[r * 32 + c4];
        }
        #pragma unroll
        for (int i = 0; i < 16; i++) {
            int idx = tid + i * 128;        // < 2048
            int c = idx & 15, d = idx >> 4;
            SWT[c * 132 + d] = W_l[d * DLL + c];
        }
        #pragma unroll
        for (int i = 0; i < 8; i++) {
            int idx = tid + i * 128;        // < 1024
            int c = idx & 7, d = idx >> 3;
            SWT[(16 + c) * 132 + d] = W_theta[d * KK + c];
        }
        #pragma unroll
        for (int i = 0; i < 2; i++) {
            int idx = tid + i * 128;
            float a = wq[idx], s = ws[idx], d = wd[idx];
            SCW[idx] = (side == 0) ? (a + d) : (s - d);
        }
    }
    __syncthreads();

    // ---- bf16 copy of h rows (vectorized): 256 chunks, 2 iters ----
    #pragma unroll
    for (int i = 0; i < 2; i++) {
        int idx = tid + i * 128;        // < 256
        int r = idx >> 4, c = idx & 15;
        const float* sr = SROW + r * 132 + c * 8;
        float4 x0 = *(const float4*)sr;
        float4 x1 = *(const float4*)(sr + 4);
        uint4 o;
        o.x = bf16pack(x0.x, x0.y); o.y = bf16pack(x0.z, x0.w);
        o.z = bf16pack(x1.x, x1.y); o.w = bf16pack(x1.z, x1.w);
        *(uint4*)(g_hb[side] + (size_t)(r0 + r) * 64 + c * 4) = o;
    }

    // ---- projection GEMM: 16 rows x 24 cols; thread = 1 row x 3 cols ----
    {
        int r = tid >> 3, cg = tid & 7;
        float acc[3] = {0.f, 0.f, 0.f};
        const float* sr = SROW + r * 132;
        #pragma unroll 4
        for (int kc = 0; kc < 32; kc++) {
            float4 x = *(const float4*)(sr + kc * 4);
            #pragma unroll
            for (int j = 0; j < 3; j++) {
                float4 w = *(const float4*)(SWT + (cg + 8 * j) * 132 + kc * 4);
                acc[j] = fmaf(x.x, w.x, acc[j]);
                acc[j] = fmaf(x.y, w.y, acc[j]);
                acc[j] = fmaf(x.z, w.z, acc[j]);
                acc[j] = fmaf(x.w, w.w, acc[j]);
            }
        }
        #pragma unroll
        for (int j = 0; j < 3; j++) {
            int c = cg + 8 * j;
            if (c < DLL) {
                float lr = tf32r(acc[j]);
                SL[r * 20 + c] = lr;
                g_l[side][(size_t)(r0 + r) * DLL + c] = lr;
            } else {
                STH[r * 12 + (c - 16)] = acc[j];
            }
        }
    }

    // ---- hn: 8 threads per row, 16 elems each (bf16-rounded) ----
    {
        int r = tid >> 3, seg = tid & 7;
        const float* sr = SROW + r * 132 + seg * 16;
        float a = 0.f;
        #pragma unroll
        for (int c4 = 0; c4 < 4; c4++) {
            float4 x = *(const float4*)(sr + c4 * 4);
            float x0 = bf16r(x.x), x1 = bf16r(x.y);
            float x2 = bf16r(x.z), x3 = bf16r(x.w);
            a = fmaf(x0, x0, a); a = fmaf(x1, x1, a);
            a = fmaf(x2, x2, a); a = fmaf(x3, x3, a);
        }
        a += __shfl_xor_sync(0xffffffffu, a, 1);
        a += __shfl_xor_sync(0xffffffffu, a, 2);
        a += __shfl_xor_sync(0xffffffffu, a, 4);
        if (seg == 0) g_hn[side][r0 + r] = a;
    }
    __syncthreads();

    // ---- ln: 16 threads ----
    if (tid < 16) {
        const float* sr = SL + tid * 20;
        float a = 0.f;
        #pragma unroll
        for (int c4 = 0; c4 < 4; c4++) {
            float4 x = *(const float4*)(sr + c4 * 4);
            a = fmaf(x.x, x.x, a); a = fmaf(x.y, x.y, a);
            a = fmaf(x.z, x.z, a); a = fmaf(x.w, x.w, a);
        }
        g_ln[side][r0 + tid] = a;
    }

    // ---- PQ + c: 16 rows x 32 cols, 4 iters; warp = one row ----
    #pragma unroll
    for (int i = 0; i < 4; i++) {
        int idx = tid + i * 128;
        int r = idx >> 5, c = idx & 31;
        float x = (side == 0) ? __ldg(&b1[c]) : 0.f;
        #pragma unroll
        for (int k = 0; k < KK; k++)
            x = fmaf(STH[r * 12 + k], SCW[k * HTH + c], x);
        float w2 = __ldg(&w2_w[c]);
        float x2 = x * x;
        g_PQ[side][(size_t)(r0 + r) * HTH + c] =
            tf32r((side == 0) ? (2.0f * C0g * w2 * x) : x);
        float v = w2 * (fmaf(C1g, x2 * x2, fmaf(C0g, x2, 0.5f * x)));
        #pragma unroll
        for (int o = 16; o > 0; o >>= 1)
            v += __shfl_xor_sync(0xffffffffu, v, o);
        if (c == 0) g_c[side][r0 + r] = v;
    }
}

// ---------------------------------------------------------------------------
// main (R12 config): 128x128 tile, 512 threads (16 warps); warp = 16x64.
// Phase A: theta+l via tf32 m16n8k8. Phase B: h Gram via bf16 m16n8k16,
// tiles fetched by cp.async overlapped with phase A.
// ---------------------------------------------------------------------------
// float-word offsets in dynamic smem
#define S_HBT 0                        // 128 x 68 u32 (bf16x2 rows)
#define S_HBS (S_HBT + 128*68)
#define S_PT  (S_HBS + 128*68)         // 128 x 36
#define S_QS  (S_PT  + 128*36)
#define S_LT  (S_QS  + 128*36)         // 128 x 20
#define S_LS  (S_LT  + 128*20)
#define S_LUT (S_LS  + 128*20)         // 2048 float2
#define S_SC  (S_LUT + 4096)           // 768
#define MAIN_SMEM ((S_SC + 768) * 4)

__global__ __launch_bounds__(512)
void main_kernel(const float* __restrict__ w2_b, float* __restrict__ out)
{
    extern __shared__ float S[];
    float* sc = S + S_SC;
    // sc: [0]=hn_t [128]=hn_s [256]=ln_t [384]=ln_s [512]=c_t [640]=c_s

    int bz  = blockIdx.z;
    int t0  = blockIdx.y * 128;
    int s0  = blockIdx.x * 128;
    int tid = threadIdx.x;
    int rt  = bz * TT + t0;
    int rs  = bz * TT + s0;

    // ---- cp.async the bf16 h tiles (overlaps with phase A) ----
    {
        unsigned dT = smem_u32(S + S_HBT);
        unsigned dS = smem_u32(S + S_HBS);
        const unsigned* gt = g_hb[0] + (size_t)rt * 64;
        const unsigned* gs = g_hb[1] + (size_t)rs * 64;
        #pragma unroll
        for (int i = 0; i < 4; i++) {
            int idx = tid + i * 512;        // < 2048
            int r = idx >> 4, c = idx & 15; // row, 16B chunk
            unsigned off = (unsigned)(r * 68 + c * 4) * 4u;
            CP_ASYNC16(dT + off, gt + r * 64 + c * 4);
            CP_ASYNC16(dS + off, gs + r * 64 + c * 4);
        }
        asm volatile("cp.async.commit_group;" ::: "memory");
    }

    // ---- stage phase-A tiles ----
    {
        const float4* pt = (const float4*)(g_PQ[0] + (size_t)rt * HTH);
        const float4* qs = (const float4*)(g_PQ[1] + (size_t)rs * HTH);
        #pragma unroll
        for (int i = 0; i < 2; i++) {
            int idx = tid + i * 512;        // < 1024
            int r = idx >> 3, c4 = idx & 7;
            *(float4*)(S + S_PT + r * 36 + c4 * 4) = pt[r * 8 + c4];
            *(float4*)(S + S_QS + r * 36 + c4 * 4) = qs[r * 8 + c4];
        }
        {
            int r = tid >> 2, c4 = tid & 3;
            const float4* lt = (const float4*)(g_l[0] + (size_t)rt * DLL);
            const float4* ls = (const float4*)(g_l[1] + (size_t)rs * DLL);
            *(float4*)(S + S_LT + r * 20 + c4 * 4) = lt[r * 4 + c4];
            *(float4*)(S + S_LS + r * 20 + c4 * 4) = ls[r * 4 + c4];
        }
        const float4* lv = (const float4*)g_lut;
        #pragma unroll
        for (int i = 0; i < 2; i++) {
            int idx = tid + i * 512;        // < 1024
            *(float4*)(S + S_LUT + idx * 4) = lv[idx];
        }
        if (tid < 128) {
            sc[tid]       = g_hn[0][rt + tid];
            sc[128 + tid] = g_hn[1][rs + tid];
            sc[256 + tid] = g_ln[0][rt + tid];
            sc[384 + tid] = g_ln[1][rs + tid];
            sc[512 + tid] = g_c [0][rt + tid];
            sc[640 + tid] = g_c [1][rs + tid];
        }
    }
    float w2b = __ldg(w2_b);
    __syncthreads();

    int wid  = tid >> 5;        // 0..15
    int lane = tid & 31;
    int g    = lane >> 2;       // 0..7
    int q    = lane & 3;        // 0..3
    int m0   = (wid & 7) * 16;  // warp rows [m0, m0+16)
    int nh   = wid >> 3;        // n-half: n-tiles [nh*8, nh*8+8)

    float ct0  = sc[512 + m0 + g],  ct1  = sc[512 + m0 + g + 8];
    float lnt0 = sc[256 + m0 + g],  lnt1 = sc[256 + m0 + g + 8];
    float hnt0 = sc[m0 + g],        hnt1 = sc[m0 + g + 8];

    // ============ Phase A: theta + l Grams -> tp[8][4] ============
    unsigned aT[4][4], aL[2][4];
    #pragma unroll
    for (int ks = 0; ks < 4; ks++) {
        const float* p0 = S + S_PT + (m0 + g) * 36 + ks * 8 + q;
        const float* p1 = S + S_PT + (m0 + g + 8) * 36 + ks * 8 + q;
        aT[ks][0] = ldsu(p0);     aT[ks][1] = ldsu(p1);
        aT[ks][2] = ldsu(p0 + 4); aT[ks][3] = ldsu(p1 + 4);
    }
    #pragma unroll
    for (int ks = 0; ks < 2; ks++) {
        const float* p0 = S + S_LT + (m0 + g) * 20 + ks * 8 + q;
        const float* p1 = S + S_LT + (m0 + g + 8) * 20 + ks * 8 + q;
        aL[ks][0] = ldsu(p0);     aL[ks][1] = ldsu(p1);
        aL[ks][2] = ldsu(p0 + 4); aL[ks][3] = ldsu(p1 + 4);
    }

    float tp[8][4];
    const float2* slut = (const float2*)(S + S_LUT);

    #pragma unroll
    for (int n = 0; n < 8; n++) {
        int n0 = (nh * 8 + n) * 8;
        float dT[4] = {0.f, 0.f, 0.f, 0.f};
        #pragma unroll
        for (int ks = 0; ks < 4; ks++) {
            const float* bp = S + S_QS + (n0 + g) * 36 + ks * 8 + q;
            unsigned b[2] = { ldsu(bp), ldsu(bp + 4) };
            mma8(dT, aT[ks], b);
        }
        float dL[4] = {0.f, 0.f, 0.f, 0.f};
        #pragma unroll
        for (int ks = 0; ks < 2; ks++) {
            const float* bp = S + S_LS + (n0 + g) * 20 + ks * 8 + q;
            unsigned b[2] = { ldsu(bp), ldsu(bp + 4) };
            mma8(dL, aL[ks], b);
        }
        int c0 = n0 + 2 * q, c1 = c0 + 1;
        float cs0  = sc[640 + c0], cs1  = sc[640 + c1];
        float lns0 = sc[384 + c0], lns1 = sc[384 + c1];
        float ctv[4]  = { ct0, ct0, ct1, ct1 };
        float csv[4]  = { cs0, cs1, cs0, cs1 };
        float lntv[4] = { lnt0, lnt0, lnt1, lnt1 };
        float lnsv[4] = { lns0, lns1, lns0, lns1 };
        #pragma unroll
        for (int e = 0; e < 4; e++) {
            float a = w2b + ctv[e] + csv[e] + dT[e];
            float u = a * a;
            float Th = a * fmaf(u, fmaf(u, fmaf(u, -0.05396825397f,
                                 0.13333333333f), -0.33333333333f), 1.0f);
            float dl2 = fmaxf(fmaf(-2.f, dL[e], lntv[e] + lnsv[e]), 0.f);
            float t   = fminf(dl2 * LUTSCL, (float)(LUTN - 1));
            int   ix  = (int)t;
            float fr  = t - (float)ix;
            float2 lv = slut[ix];
            tp[n][e] = -Th * fmaf(fr, lv.y, lv.x);
        }
    }

    // ============ Phase B: h Gram (bf16, K=128 -> 8 ksteps) ============
    asm volatile("cp.async.wait_group 0;" ::: "memory");
    __syncthreads();

    const unsigned* HBT = (const unsigned*)(S + S_HBT);
    const unsigned* HBS = (const unsigned*)(S + S_HBS);

    float acc[8][4];
    #pragma unroll
    for (int n = 0; n < 8; n++)
        #pragma unroll
        for (int e = 0; e < 4; e++) acc[n][e] = 0.f;

    #pragma unroll 4
    for (int ks = 0; ks < 8; ks++) {
        int kb = ks * 8;
        const unsigned* pT = HBT + (m0 + g) * 68 + kb + q;
        unsigned a[4] = { pT[0], pT[8 * 68], pT[4], pT[8 * 68 + 4] };
        #pragma unroll
        for (int n = 0; n < 8; n++) {
            const unsigned* pS = HBS + ((nh * 8 + n) * 8 + g) * 68 + kb + q;
            unsigned b[2] = { pS[0], pS[4] };
            mma16(acc[n], a, b);
        }
    }

    // ============ epilogue ============
    {
        size_t orow0 = ((size_t)(bz * TT + t0 + m0 + g)) * TT + s0;
        size_t orow1 = orow0 + (size_t)8 * TT;
        #pragma unroll
        for (int n = 0; n < 8; n++) {
            int c0 = (nh * 8 + n) * 8 + 2 * q;
            float hns0 = sc[128 + c0], hns1 = sc[128 + c0 + 1];
            float d0 = fmaxf(fmaf(-2.f, acc[n][0], hnt0 + hns0), 0.f) + EPS2;
            float d1 = fmaxf(fmaf(-2.f, acc[n][1], hnt0 + hns1), 0.f) + EPS2;
            float d2 = fmaxf(fmaf(-2.f, acc[n][2], hnt1 + hns0), 0.f) + EPS2;
            float d3 = fmaxf(fmaf(-2.f, acc[n][3], hnt1 + hns1), 0.f) + EPS2;
            float2 v0 = make_float2(tp[n][0] * rsqrtf(d0), tp[n][1] * rsqrtf(d1));
            float2 v1 = make_float2(tp[n][2] * rsqrtf(d2), tp[n][3] * rsqrtf(d3));
            *(float2*)(out + orow0 + c0) = v0;
            *(float2*)(out + orow1 + c0) = v1;
        }
    }
}

// ---------------------------------------------------------------------------
extern "C" void kernel_launch(void* const* d_in, const int* in_sizes, int n_in,
                              void* d_out, int out_size)
{
    (void)in_sizes; (void)n_in; (void)out_size;
    const float* h       = (const float*)d_in[0];
    const float* hsrc    = (const float*)d_in[1];
    const float* W_l     = (const float*)d_in[2];
    const float* W_theta = (const float*)d_in[3];
    const float* phi1_w  = (const float*)d_in[4];
    const float* phi1_b  = (const float*)d_in[5];
    const float* phi2_w  = (const float*)d_in[6];
    const float* phi2_b  = (const float*)d_in[7];
    const float* wq      = (const float*)d_in[8];
    const float* ws      = (const float*)d_in[9];
    const float* wd      = (const float*)d_in[10];
    const float* b1      = (const float*)d_in[11];
    const float* w2_w    = (const float*)d_in[12];
    const float* w2_b    = (const float*)d_in[13];
    float* out = (float*)d_out;

    cudaFuncSetAttribute(prep_kernel,
                         cudaFuncAttributeMaxDynamicSharedMemorySize, PREP_SMEM);
    cudaFuncSetAttribute(main_kernel,
                         cudaFuncAttributeMaxDynamicSharedMemorySize, MAIN_SMEM);

    prep_kernel<<<dim3(256, 3), 128, PREP_SMEM>>>(h, hsrc, W_l, W_theta,
                                                  wq, ws, wd, b1, w2_w,
                                                  phi1_w, phi1_b, phi2_w, phi2_b);
    main_kernel<<<dim3(4, 4, BB), 512, MAIN_SMEM>>>(w2_b, out);
}

// round 15
// speedup vs baseline: 1.0949x; 1.0949x over previous
#include <cuda_runtime.h>
#include <math.h>
#include <stdint.h>

// Problem constants
#define BB   8
#define TT   512
#define DD   128
#define DLL  16
#define KK   8
#define HTH  32
#define NROWS (BB*TT)   // 4096
#define EPS2 0.0001f

// gelu Taylor: gelu(x) = 0.5x + C0 x^2 + C1 x^4 (|x| small)
#define C0g  0.3989422804014327f
#define C1g  (-0.06649038006690545f)

// Phi LUT: 2048 entries over dl2 in [0,16), step 1/128
#define LUTN   2048
#define LUTSCL 128.0f

// Scratch
__device__ __align__(16) float    g_l[2][NROWS*DLL];   // l vectors (tf32-rounded)
__device__ __align__(16) float    g_PQ[2][NROWS*HTH];  // theta vectors (tf32-rounded)
__device__ __align__(16) unsigned g_hb[2][NROWS*64];   // h rows packed bf16x2
__device__ float  g_hn[2][NROWS];
__device__ float  g_ln[2][NROWS];
__device__ float  g_c[2][NROWS];
__device__ __align__(16) float2 g_lut[LUTN];

// ---------------------------------------------------------------------------
// helpers
// ---------------------------------------------------------------------------
__device__ __forceinline__ float tf32r(float x) {
    unsigned u;
    asm("cvt.rna.tf32.f32 %0, %1;" : "=r"(u) : "f"(x));
    return __uint_as_float(u);
}

__device__ __forceinline__ float bf16r(float x) {
    unsigned p;
    asm("cvt.rn.bf16x2.f32 %0, %1, %2;" : "=r"(p) : "f"(x), "f"(x));
    return __uint_as_float(p << 16);
}

__device__ __forceinline__ unsigned bf16pack(float lo, float hi) {
    unsigned p;
    asm("cvt.rn.bf16x2.f32 %0, %1, %2;" : "=r"(p) : "f"(hi), "f"(lo));
    return p;
}

// m16n8k8 tf32 MMA, fp32 accumulate
__device__ __forceinline__ void mma8(float* d, const unsigned* a, const unsigned* b) {
    asm volatile(
        "mma.sync.aligned.m16n8k8.row.col.f32.tf32.tf32.f32 "
        "{%0,%1,%2,%3},{%4,%5,%6,%7},{%8,%9},{%0,%1,%2,%3};"
        : "+f"(d[0]), "+f"(d[1]), "+f"(d[2]), "+f"(d[3])
        : "r"(a[0]), "r"(a[1]), "r"(a[2]), "r"(a[3]), "r"(b[0]), "r"(b[1]));
}

// m16n8k16 bf16 MMA, fp32 accumulate
__device__ __forceinline__ void mma16(float* d, const unsigned* a, const unsigned* b) {
    asm volatile(
        "mma.sync.aligned.m16n8k16.row.col.f32.bf16.bf16.f32 "
        "{%0,%1,%2,%3},{%4,%5,%6,%7},{%8,%9},{%0,%1,%2,%3};"
        : "+f"(d[0]), "+f"(d[1]), "+f"(d[2]), "+f"(d[3])
        : "r"(a[0]), "r"(a[1]), "r"(a[2]), "r"(a[3]), "r"(b[0]), "r"(b[1]));
}

__device__ __forceinline__ unsigned ldsu(const float* p) {
    return __float_as_uint(*p);
}

__device__ __forceinline__ unsigned smem_u32(const void* p) {
    unsigned a;
    asm("{ .reg .u64 t; cvta.to.shared.u64 t, %1; cvt.u32.u64 %0, t; }"
        : "=r"(a) : "l"(p));
    return a;
}

#define CP_ASYNC16(dst_u32, src) \
    asm volatile("cp.async.ca.shared.global [%0], [%1], 16;" \
                 :: "r"(dst_u32), "l"(src) : "memory")

__device__ __forceinline__ float gelu_exact(float x) {
    return 0.5f * x * (1.0f + erff(x * 0.7071067811865475f));
}

// ---------------------------------------------------------------------------
// prep: grid (64, 3), block 256. 64 rows per block; all phases ~2x shorter
// than the R12 128-thread version. LUT on side 2.
// ---------------------------------------------------------------------------
#define P_SROW 0                       // 64 x 132
#define P_SWT  (P_SROW + 64*132)       // 24 x 132 (transposed weights)
#define P_SL   (P_SWT  + 24*132)       // 64 x 20
#define P_STH  (P_SL   + 64*20)        // 64 x 12
#define P_SCW  (P_STH  + 64*12)        // 8 x 32
#define PREP_SMEM ((P_SCW + 256) * 4)

__global__ __launch_bounds__(256)
void prep_kernel(const float* __restrict__ h,
                 const float* __restrict__ hsrc,
                 const float* __restrict__ W_l,
                 const float* __restrict__ W_theta,
                 const float* __restrict__ wq,
                 const float* __restrict__ ws,
                 const float* __restrict__ wd,
                 const float* __restrict__ b1,
                 const float* __restrict__ w2_w,
                 const float* __restrict__ phi1_w,
                 const float* __restrict__ phi1_b,
                 const float* __restrict__ phi2_w,
                 const float* __restrict__ phi2_b)
{
    int side = blockIdx.y;
    int tid  = threadIdx.x;

    if (side == 2) {
        // LUT: 64 blocks x 8 warps x 4 entries = 2048
        int wid = tid >> 5, lane = tid & 31;
        float w = phi1_w[lane], b = phi1_b[lane], v = phi2_w[lane];
        float ph2b = phi2_b[0];
        #pragma unroll
        for (int sub = 0; sub < 4; sub++) {
            int e = blockIdx.x * 32 + wid * 4 + sub;
            float x0 = (float)e       * (1.0f / LUTSCL);
            float x1 = (float)(e + 1) * (1.0f / LUTSCL);
            float s0 = gelu_exact(fmaf(x0, w, b)) * v;
            float s1 = gelu_exact(fmaf(x1, w, b)) * v;
            #pragma unroll
            for (int o = 16; o > 0; o >>= 1) {
                s0 += __shfl_xor_sync(0xffffffffu, s0, o);
                s1 += __shfl_xor_sync(0xffffffffu, s1, o);
            }
            if (lane == 0) {
                float a0 = s0 + ph2b, a1 = s1 + ph2b;
                float c0 = fmaxf(a0, 0.f) + log1pf(expf(-fabsf(a0)));
                float c1 = fmaxf(a1, 0.f) + log1pf(expf(-fabsf(a1)));
                float p0 = expf(-c0 * x0);
                float p1 = expf(-c1 * x1);
                g_lut[e] = make_float2(p0, p1 - p0);
            }
        }
        return;
    }

    extern __shared__ float ps[];
    float* SROW = ps + P_SROW;
    float* SWT  = ps + P_SWT;
    float* SL   = ps + P_SL;
    float* STH  = ps + P_STH;
    float* SCW  = ps + P_SCW;

    int r0 = blockIdx.x * 64;
    const float* src = (side == 0) ? h : hsrc;

    // ---- stage ----
    {
        const float4* sv = (const float4*)(src + (size_t)r0 * DD);
        #pragma unroll
        for (int i = 0; i < 8; i++) {
            int idx = tid + i * 256;        // < 2048 f4
            int r = idx >> 5, c4 = idx & 31;
            *(float4*)(SROW + r * 132 + c4 * 4) = sv[r * 32 + c4];
        }
        #pragma unroll
        for (int i = 0; i < 8; i++) {
            int idx = tid + i * 256;        // < 2048
            int c = idx & 15, d = idx >> 4;
            SWT[c * 132 + d] = W_l[d * DLL + c];
        }
        #pragma unroll
        for (int i = 0; i < 4; i++) {
            int idx = tid + i * 256;        // < 1024
            int c = idx & 7, d = idx >> 3;
            SWT[(16 + c) * 132 + d] = W_theta[d * KK + c];
        }
        {
            float a = wq[tid], s = ws[tid], d = wd[tid];
            SCW[tid] = (side == 0) ? (a + d) : (s - d);
        }
    }
    __syncthreads();

    // ---- bf16 copy of h rows (vectorized): 1024 chunks of 8 floats ----
    #pragma unroll
    for (int i = 0; i < 4; i++) {
        int idx = tid + i * 256;        // < 1024
        int r = idx >> 4, c = idx & 15;
        const float* sr = SROW + r * 132 + c * 8;
        float4 x0 = *(const float4*)sr;
        float4 x1 = *(const float4*)(sr + 4);
        uint4 o;
        o.x = bf16pack(x0.x, x0.y); o.y = bf16pack(x0.z, x0.w);
        o.z = bf16pack(x1.x, x1.y); o.w = bf16pack(x1.z, x1.w);
        *(uint4*)(g_hb[side] + (size_t)(r0 + r) * 64 + c * 4) = o;
    }

    // ---- projection GEMM: 64 rows x 24 cols; thread = 1 row x 6 cols ----
    {
        int r = tid >> 2, cg = tid & 3;     // 64 rows x 4 col-groups
        float acc[6] = {0.f, 0.f, 0.f, 0.f, 0.f, 0.f};
        const float* sr = SROW + r * 132;
        #pragma unroll 4
        for (int kc = 0; kc < 32; kc++) {
            float4 x = *(const float4*)(sr + kc * 4);
            #pragma unroll
            for (int j = 0; j < 6; j++) {
                float4 w = *(const float4*)(SWT + (cg + 4 * j) * 132 + kc * 4);
                acc[j] = fmaf(x.x, w.x, acc[j]);
                acc[j] = fmaf(x.y, w.y, acc[j]);
                acc[j] = fmaf(x.z, w.z, acc[j]);
                acc[j] = fmaf(x.w, w.w, acc[j]);
            }
        }
        #pragma unroll
        for (int j = 0; j < 6; j++) {
            int c = cg + 4 * j;
            if (c < DLL) {
                float lr = tf32r(acc[j]);
                SL[r * 20 + c] = lr;
                g_l[side][(size_t)(r0 + r) * DLL + c] = lr;
            } else {
                STH[r * 12 + (c - 16)] = acc[j];
            }
        }
    }

    // ---- hn: 4 threads per row, 32 elems each (bf16-rounded) ----
    {
        int r = tid >> 2, seg = tid & 3;
        const float* sr = SROW + r * 132 + seg * 32;
        float a = 0.f;
        #pragma unroll
        for (int c4 = 0; c4 < 8; c4++) {
            float4 x = *(const float4*)(sr + c4 * 4);
            float x0 = bf16r(x.x), x1 = bf16r(x.y);
            float x2 = bf16r(x.z), x3 = bf16r(x.w);
            a = fmaf(x0, x0, a); a = fmaf(x1, x1, a);
            a = fmaf(x2, x2, a); a = fmaf(x3, x3, a);
        }
        a += __shfl_xor_sync(0xffffffffu, a, 1);
        a += __shfl_xor_sync(0xffffffffu, a, 2);
        if (seg == 0) g_hn[side][r0 + r] = a;
    }
    __syncthreads();

    // ---- ln: 64 threads, one row each ----
    if (tid < 64) {
        const float* sr = SL + tid * 20;
        float a = 0.f;
        #pragma unroll
        for (int c4 = 0; c4 < 4; c4++) {
            float4 x = *(const float4*)(sr + c4 * 4);
            a = fmaf(x.x, x.x, a); a = fmaf(x.y, x.y, a);
            a = fmaf(x.z, x.z, a); a = fmaf(x.w, x.w, a);
        }
        g_ln[side][r0 + tid] = a;
    }

    // ---- PQ + c: 64 rows x 32 cols, 8 iters; warp = one row ----
    #pragma unroll
    for (int i = 0; i < 8; i++) {
        int idx = tid + i * 256;        // < 2048
        int r = idx >> 5, c = idx & 31;
        float x = (side == 0) ? __ldg(&b1[c]) : 0.f;
        #pragma unroll
        for (int k = 0; k < KK; k++)
            x = fmaf(STH[r * 12 + k], SCW[k * HTH + c], x);
        float w2 = __ldg(&w2_w[c]);
        float x2 = x * x;
        g_PQ[side][(size_t)(r0 + r) * HTH + c] =
            tf32r((side == 0) ? (2.0f * C0g * w2 * x) : x);
        float v = w2 * (fmaf(C1g, x2 * x2, fmaf(C0g, x2, 0.5f * x)));
        #pragma unroll
        for (int o = 16; o > 0; o >>= 1)
            v += __shfl_xor_sync(0xffffffffu, v, o);
        if (c == 0) g_c[side][r0 + r] = v;
    }
}

// ---------------------------------------------------------------------------
// main (R12 config, unchanged): 128x128 tile, 512 threads (16 warps);
// warp = 16x64. Phase A: theta+l via tf32 m16n8k8. Phase B: h Gram via
// bf16 m16n8k16, tiles fetched by cp.async overlapped with phase A.
// ---------------------------------------------------------------------------
// float-word offsets in dynamic smem
#define S_HBT 0                        // 128 x 68 u32 (bf16x2 rows)
#define S_HBS (S_HBT + 128*68)
#define S_PT  (S_HBS + 128*68)         // 128 x 36
#define S_QS  (S_PT  + 128*36)
#define S_LT  (S_QS  + 128*36)         // 128 x 20
#define S_LS  (S_LT  + 128*20)
#define S_LUT (S_LS  + 128*20)         // 2048 float2
#define S_SC  (S_LUT + 4096)           // 768
#define MAIN_SMEM ((S_SC + 768) * 4)

__global__ __launch_bounds__(512)
void main_kernel(const float* __restrict__ w2_b, float* __restrict__ out)
{
    extern __shared__ float S[];
    float* sc = S + S_SC;
    // sc: [0]=hn_t [128]=hn_s [256]=ln_t [384]=ln_s [512]=c_t [640]=c_s

    int bz  = blockIdx.z;
    int t0  = blockIdx.y * 128;
    int s0  = blockIdx.x * 128;
    int tid = threadIdx.x;
    int rt  = bz * TT + t0;
    int rs  = bz * TT + s0;

    // ---- cp.async the bf16 h tiles (overlaps with phase A) ----
    {
        unsigned dT = smem_u32(S + S_HBT);
        unsigned dS = smem_u32(S + S_HBS);
        const unsigned* gt = g_hb[0] + (size_t)rt * 64;
        const unsigned* gs = g_hb[1] + (size_t)rs * 64;
        #pragma unroll
        for (int i = 0; i < 4; i++) {
            int idx = tid + i * 512;        // < 2048
            int r = idx >> 4, c = idx & 15; // row, 16B chunk
            unsigned off = (unsigned)(r * 68 + c * 4) * 4u;
            CP_ASYNC16(dT + off, gt + r * 64 + c * 4);
            CP_ASYNC16(dS + off, gs + r * 64 + c * 4);
        }
        asm volatile("cp.async.commit_group;" ::: "memory");
    }

    // ---- stage phase-A tiles ----
    {
        const float4* pt = (const float4*)(g_PQ[0] + (size_t)rt * HTH);
        const float4* qs = (const float4*)(g_PQ[1] + (size_t)rs * HTH);
        #pragma unroll
        for (int i = 0; i < 2; i++) {
            int idx = tid + i * 512;        // < 1024
            int r = idx >> 3, c4 = idx & 7;
            *(float4*)(S + S_PT + r * 36 + c4 * 4) = pt[r * 8 + c4];
            *(float4*)(S + S_QS + r * 36 + c4 * 4) = qs[r * 8 + c4];
        }
        {
            int r = tid >> 2, c4 = tid & 3;
            const float4* lt = (const float4*)(g_l[0] + (size_t)rt * DLL);
            const float4* ls = (const float4*)(g_l[1] + (size_t)rs * DLL);
            *(float4*)(S + S_LT + r * 20 + c4 * 4) = lt[r * 4 + c4];
            *(float4*)(S + S_LS + r * 20 + c4 * 4) = ls[r * 4 + c4];
        }
        const float4* lv = (const float4*)g_lut;
        #pragma unroll
        for (int i = 0; i < 2; i++) {
            int idx = tid + i * 512;        // < 1024
            *(float4*)(S + S_LUT + idx * 4) = lv[idx];
        }
        if (tid < 128) {
            sc[tid]       = g_hn[0][rt + tid];
            sc[128 + tid] = g_hn[1][rs + tid];
            sc[256 + tid] = g_ln[0][rt + tid];
            sc[384 + tid] = g_ln[1][rs + tid];
            sc[512 + tid] = g_c [0][rt + tid];
            sc[640 + tid] = g_c [1][rs + tid];
        }
    }
    float w2b = __ldg(w2_b);
    __syncthreads();

    int wid  = tid >> 5;        // 0..15
    int lane = tid & 31;
    int g    = lane >> 2;       // 0..7
    int q    = lane & 3;        // 0..3
    int m0   = (wid & 7) * 16;  // warp rows [m0, m0+16)
    int nh   = wid >> 3;        // n-half: n-tiles [nh*8, nh*8+8)

    float ct0  = sc[512 + m0 + g],  ct1  = sc[512 + m0 + g + 8];
    float lnt0 = sc[256 + m0 + g],  lnt1 = sc[256 + m0 + g + 8];
    float hnt0 = sc[m0 + g],        hnt1 = sc[m0 + g + 8];

    // ============ Phase A: theta + l Grams -> tp[8][4] ============
    unsigned aT[4][4], aL[2][4];
    #pragma unroll
    for (int ks = 0; ks < 4; ks++) {
        const float* p0 = S + S_PT + (m0 + g) * 36 + ks * 8 + q;
        const float* p1 = S + S_PT + (m0 + g + 8) * 36 + ks * 8 + q;
        aT[ks][0] = ldsu(p0);     aT[ks][1] = ldsu(p1);
        aT[ks][2] = ldsu(p0 + 4); aT[ks][3] = ldsu(p1 + 4);
    }
    #pragma unroll
    for (int ks = 0; ks < 2; ks++) {
        const float* p0 = S + S_LT + (m0 + g) * 20 + ks * 8 + q;
        const float* p1 = S + S_LT + (m0 + g + 8) * 20 + ks * 8 + q;
        aL[ks][0] = ldsu(p0);     aL[ks][1] = ldsu(p1);
        aL[ks][2] = ldsu(p0 + 4); aL[ks][3] = ldsu(p1 + 4);
    }

    float tp[8][4];
    const float2* slut = (const float2*)(S + S_LUT);

    #pragma unroll
    for (int n = 0; n < 8; n++) {
        int n0 = (nh * 8 + n) * 8;
        float dT[4] = {0.f, 0.f, 0.f, 0.f};
        #pragma unroll
        for (int ks = 0; ks < 4; ks++) {
            const float* bp = S + S_QS + (n0 + g) * 36 + ks * 8 + q;
            unsigned b[2] = { ldsu(bp), ldsu(bp + 4) };
            mma8(dT, aT[ks], b);
        }
        float dL[4] = {0.f, 0.f, 0.f, 0.f};
        #pragma unroll
        for (int ks = 0; ks < 2; ks++) {
            const float* bp = S + S_LS + (n0 + g) * 20 + ks * 8 + q;
            unsigned b[2] = { ldsu(bp), ldsu(bp + 4) };
            mma8(dL, aL[ks], b);
        }
        int c0 = n0 + 2 * q, c1 = c0 + 1;
        float cs0  = sc[640 + c0], cs1  = sc[640 + c1];
        float lns0 = sc[384 + c0], lns1 = sc[384 + c1];
        float ctv[4]  = { ct0, ct0, ct1, ct1 };
        float csv[4]  = { cs0, cs1, cs0, cs1 };
        float lntv[4] = { lnt0, lnt0, lnt1, lnt1 };
        float lnsv[4] = { lns0, lns1, lns0, lns1 };
        #pragma unroll
        for (int e = 0; e < 4; e++) {
            float a = w2b + ctv[e] + csv[e] + dT[e];
            float u = a * a;
            float Th = a * fmaf(u, fmaf(u, fmaf(u, -0.05396825397f,
                                 0.13333333333f), -0.33333333333f), 1.0f);
            float dl2 = fmaxf(fmaf(-2.f, dL[e], lntv[e] + lnsv[e]), 0.f);
            float t   = fminf(dl2 * LUTSCL, (float)(LUTN - 1));
            int   ix  = (int)t;
            float fr  = t - (float)ix;
            float2 lv = slut[ix];
            tp[n][e] = -Th * fmaf(fr, lv.y, lv.x);
        }
    }

    // ============ Phase B: h Gram (bf16, K=128 -> 8 ksteps) ============
    asm volatile("cp.async.wait_group 0;" ::: "memory");
    __syncthreads();

    const unsigned* HBT = (const unsigned*)(S + S_HBT);
    const unsigned* HBS = (const unsigned*)(S + S_HBS);

    float acc[8][4];
    #pragma unroll
    for (int n = 0; n < 8; n++)
        #pragma unroll
        for (int e = 0; e < 4; e++) acc[n][e] = 0.f;

    #pragma unroll 4
    for (int ks = 0; ks < 8; ks++) {
        int kb = ks * 8;
        const unsigned* pT = HBT + (m0 + g) * 68 + kb + q;
        unsigned a[4] = { pT[0], pT[8 * 68], pT[4], pT[8 * 68 + 4] };
        #pragma unroll
        for (int n = 0; n < 8; n++) {
            const unsigned* pS = HBS + ((nh * 8 + n) * 8 + g) * 68 + kb + q;
            unsigned b[2] = { pS[0], pS[4] };
            mma16(acc[n], a, b);
        }
    }

    // ============ epilogue ============
    {
        size_t orow0 = ((size_t)(bz * TT + t0 + m0 + g)) * TT + s0;
        size_t orow1 = orow0 + (size_t)8 * TT;
        #pragma unroll
        for (int n = 0; n < 8; n++) {
            int c0 = (nh * 8 + n) * 8 + 2 * q;
            float hns0 = sc[128 + c0], hns1 = sc[128 + c0 + 1];
            float d0 = fmaxf(fmaf(-2.f, acc[n][0], hnt0 + hns0), 0.f) + EPS2;
            float d1 = fmaxf(fmaf(-2.f, acc[n][1], hnt0 + hns1), 0.f) + EPS2;
            float d2 = fmaxf(fmaf(-2.f, acc[n][2], hnt1 + hns0), 0.f) + EPS2;
            float d3 = fmaxf(fmaf(-2.f, acc[n][3], hnt1 + hns1), 0.f) + EPS2;
            float2 v0 = make_float2(tp[n][0] * rsqrtf(d0), tp[n][1] * rsqrtf(d1));
            float2 v1 = make_float2(tp[n][2] * rsqrtf(d2), tp[n][3] * rsqrtf(d3));
            *(float2*)(out + orow0 + c0) = v0;
            *(float2*)(out + orow1 + c0) = v1;
        }
    }
}

// ---------------------------------------------------------------------------
extern "C" void kernel_launch(void* const* d_in, const int* in_sizes, int n_in,
                              void* d_out, int out_size)
{
    (void)in_sizes; (void)n_in; (void)out_size;
    const float* h       = (const float*)d_in[0];
    const float* hsrc    = (const float*)d_in[1];
    const float* W_l     = (const float*)d_in[2];
    const float* W_theta = (const float*)d_in[3];
    const float* phi1_w  = (const float*)d_in[4];
    const float* phi1_b  = (const float*)d_in[5];
    const float* phi2_w  = (const float*)d_in[6];
    const float* phi2_b  = (const float*)d_in[7];
    const float* wq      = (const float*)d_in[8];
    const float* ws      = (const float*)d_in[9];
    const float* wd      = (const float*)d_in[10];
    const float* b1      = (const float*)d_in[11];
    const float* w2_w    = (const float*)d_in[12];
    const float* w2_b    = (const float*)d_in[13];
    float* out = (float*)d_out;

    cudaFuncSetAttribute(prep_kernel,
                         cudaFuncAttributeMaxDynamicSharedMemorySize, PREP_SMEM);
    cudaFuncSetAttribute(main_kernel,
                         cudaFuncAttributeMaxDynamicSharedMemorySize, MAIN_SMEM);

    prep_kernel<<<dim3(64, 3), 256, PREP_SMEM>>>(h, hsrc, W_l, W_theta,
                                                 wq, ws, wd, b1, w2_w,
                                                 phi1_w, phi1_b, phi2_w, phi2_b);
    main_kernel<<<dim3(4, 4, BB), 512, MAIN_SMEM>>>(w2_b, out);
}

// round 16
// speedup vs baseline: 1.2137x; 1.1085x over previous
#include <cuda_runtime.h>
#include <math.h>
#include <stdint.h>

// Problem constants
#define BB   8
#define TT   512
#define DD   128
#define DLL  16
#define KK   8
#define HTH  32
#define NROWS (BB*TT)   // 4096
#define EPS2 0.0001f

// gelu Taylor: gelu(x) = 0.5x + C0 x^2 + C1 x^4 (|x| small)
#define C0g  0.3989422804014327f
#define C1g  (-0.06649038006690545f)

// Phi LUT: 2048 entries over dl2 in [0,16), step 1/128
#define LUTN   2048
#define LUTSCL 128.0f

// Scratch
__device__ __align__(16) float    g_l[2][NROWS*DLL];   // l vectors (tf32-rounded)
__device__ __align__(16) float    g_PQ[2][NROWS*HTH];  // theta vectors (tf32-rounded)
__device__ __align__(16) unsigned g_hb[2][NROWS*64];   // h rows packed bf16x2
__device__ float  g_hn[2][NROWS];
__device__ float  g_ln[2][NROWS];
__device__ float  g_c[2][NROWS];
__device__ __align__(16) float2 g_lut[LUTN];

// ---------------------------------------------------------------------------
// helpers
// ---------------------------------------------------------------------------
__device__ __forceinline__ float tf32r(float x) {
    unsigned u;
    asm("cvt.rna.tf32.f32 %0, %1;" : "=r"(u) : "f"(x));
    return __uint_as_float(u);
}

__device__ __forceinline__ float bf16r(float x) {
    unsigned p;
    asm("cvt.rn.bf16x2.f32 %0, %1, %2;" : "=r"(p) : "f"(x), "f"(x));
    return __uint_as_float(p << 16);
}

__device__ __forceinline__ unsigned bf16pack(float lo, float hi) {
    unsigned p;
    asm("cvt.rn.bf16x2.f32 %0, %1, %2;" : "=r"(p) : "f"(hi), "f"(lo));
    return p;
}

// m16n8k8 tf32 MMA, fp32 accumulate
__device__ __forceinline__ void mma8(float* d, const unsigned* a, const unsigned* b) {
    asm volatile(
        "mma.sync.aligned.m16n8k8.row.col.f32.tf32.tf32.f32 "
        "{%0,%1,%2,%3},{%4,%5,%6,%7},{%8,%9},{%0,%1,%2,%3};"
        : "+f"(d[0]), "+f"(d[1]), "+f"(d[2]), "+f"(d[3])
        : "r"(a[0]), "r"(a[1]), "r"(a[2]), "r"(a[3]), "r"(b[0]), "r"(b[1]));
}

// m16n8k16 bf16 MMA, fp32 accumulate
__device__ __forceinline__ void mma16(float* d, const unsigned* a, const unsigned* b) {
    asm volatile(
        "mma.sync.aligned.m16n8k16.row.col.f32.bf16.bf16.f32 "
        "{%0,%1,%2,%3},{%4,%5,%6,%7},{%8,%9},{%0,%1,%2,%3};"
        : "+f"(d[0]), "+f"(d[1]), "+f"(d[2]), "+f"(d[3])
        : "r"(a[0]), "r"(a[1]), "r"(a[2]), "r"(a[3]), "r"(b[0]), "r"(b[1]));
}

__device__ __forceinline__ unsigned ldsu(const float* p) {
    return __float_as_uint(*p);
}

__device__ __forceinline__ unsigned smem_u32(const void* p) {
    unsigned a;
    asm("{ .reg .u64 t; cvta.to.shared.u64 t, %1; cvt.u32.u64 %0, t; }"
        : "=r"(a) : "l"(p));
    return a;
}

#define CP_ASYNC16(dst_u32, src) \
    asm volatile("cp.async.ca.shared.global [%0], [%1], 16;" \
                 :: "r"(dst_u32), "l"(src) : "memory")

__device__ __forceinline__ float gelu_exact(float x) {
    return 0.5f * x * (1.0f + erff(x * 0.7071067811865475f));
}

// ---------------------------------------------------------------------------
// prep: grid (64, 3), block 128. (R12 version, verbatim — known best)
// ---------------------------------------------------------------------------
#define P_SROW 0                       // 64 x 132
#define P_SWT  (P_SROW + 64*132)       // 24 x 132 (transposed weights)
#define P_SL   (P_SWT  + 24*132)       // 64 x 20
#define P_STH  (P_SL   + 64*20)        // 64 x 12
#define P_SCW  (P_STH  + 64*12)        // 8 x 32
#define PREP_SMEM ((P_SCW + 256) * 4)

__global__ __launch_bounds__(128)
void prep_kernel(const float* __restrict__ h,
                 const float* __restrict__ hsrc,
                 const float* __restrict__ W_l,
                 const float* __restrict__ W_theta,
                 const float* __restrict__ wq,
                 const float* __restrict__ ws,
                 const float* __restrict__ wd,
                 const float* __restrict__ b1,
                 const float* __restrict__ w2_w,
                 const float* __restrict__ phi1_w,
                 const float* __restrict__ phi1_b,
                 const float* __restrict__ phi2_w,
                 const float* __restrict__ phi2_b)
{
    int side = blockIdx.y;
    int tid  = threadIdx.x;

    if (side == 2) {
        int wid = tid >> 5, lane = tid & 31;
        float w = phi1_w[lane], b = phi1_b[lane], v = phi2_w[lane];
        float ph2b = phi2_b[0];
        #pragma unroll
        for (int sub = 0; sub < 8; sub++) {
            int e = blockIdx.x * 32 + wid * 8 + sub;
            float x0 = (float)e       * (1.0f / LUTSCL);
            float x1 = (float)(e + 1) * (1.0f / LUTSCL);
            float s0 = gelu_exact(fmaf(x0, w, b)) * v;
            float s1 = gelu_exact(fmaf(x1, w, b)) * v;
            #pragma unroll
            for (int o = 16; o > 0; o >>= 1) {
                s0 += __shfl_xor_sync(0xffffffffu, s0, o);
                s1 += __shfl_xor_sync(0xffffffffu, s1, o);
            }
            if (lane == 0) {
                float a0 = s0 + ph2b, a1 = s1 + ph2b;
                float c0 = fmaxf(a0, 0.f) + log1pf(expf(-fabsf(a0)));
                float c1 = fmaxf(a1, 0.f) + log1pf(expf(-fabsf(a1)));
                float p0 = expf(-c0 * x0);
                float p1 = expf(-c1 * x1);
                g_lut[e] = make_float2(p0, p1 - p0);
            }
        }
        return;
    }

    extern __shared__ float ps[];
    float* SROW = ps + P_SROW;
    float* SWT  = ps + P_SWT;
    float* SL   = ps + P_SL;
    float* STH  = ps + P_STH;
    float* SCW  = ps + P_SCW;

    int r0 = blockIdx.x * 64;
    const float* src = (side == 0) ? h : hsrc;

    {
        const float4* sv = (const float4*)(src + (size_t)r0 * DD);
        #pragma unroll
        for (int i = 0; i < 16; i++) {
            int idx = tid + i * 128;
            int r = idx >> 5, c4 = idx & 31;
            *(float4*)(SROW + r * 132 + c4 * 4) = sv[r * 32 + c4];
        }
        #pragma unroll
        for (int i = 0; i < 16; i++) {
            int idx = tid + i * 128;
            int c = idx & 15, d = idx >> 4;
            SWT[c * 132 + d] = W_l[d * DLL + c];
        }
        #pragma unroll
        for (int i = 0; i < 8; i++) {
            int idx = tid + i * 128;
            int c = idx & 7, d = idx >> 3;
            SWT[(16 + c) * 132 + d] = W_theta[d * KK + c];
        }
        #pragma unroll
        for (int i = 0; i < 2; i++) {
            int idx = tid + i * 128;
            float a = wq[idx], s = ws[idx], d = wd[idx];
            SCW[idx] = (side == 0) ? (a + d) : (s - d);
        }
    }
    __syncthreads();

    // bf16 copy of h rows (vectorized)
    #pragma unroll
    for (int i = 0; i < 8; i++) {
        int idx = tid + i * 128;        // < 1024
        int r = idx >> 4, c = idx & 15;
        const float* sr = SROW + r * 132 + c * 8;
        float4 x0 = *(const float4*)sr;
        float4 x1 = *(const float4*)(sr + 4);
        uint4 o;
        o.x = bf16pack(x0.x, x0.y); o.y = bf16pack(x0.z, x0.w);
        o.z = bf16pack(x1.x, x1.y); o.w = bf16pack(x1.z, x1.w);
        *(uint4*)(g_hb[side] + (size_t)(r0 + r) * 64 + c * 4) = o;
    }

    {
        int rg = tid >> 3, cg = tid & 7;
        float acc[4][3];
        #pragma unroll
        for (int i = 0; i < 4; i++)
            #pragma unroll
            for (int j = 0; j < 3; j++) acc[i][j] = 0.f;

        const float* sr = SROW + (rg * 4) * 132;
        #pragma unroll 4
        for (int kc = 0; kc < 32; kc++) {
            float4 x[4], w[3];
            #pragma unroll
            for (int i = 0; i < 4; i++)
                x[i] = *(const float4*)(sr + i * 132 + kc * 4);
            #pragma unroll
            for (int j = 0; j < 3; j++)
                w[j] = *(const float4*)(SWT + (cg + 8 * j) * 132 + kc * 4);
            #pragma unroll
            for (int i = 0; i < 4; i++)
                #pragma unroll
                for (int j = 0; j < 3; j++) {
                    acc[i][j] = fmaf(x[i].x, w[j].x, acc[i][j]);
                    acc[i][j] = fmaf(x[i].y, w[j].y, acc[i][j]);
                    acc[i][j] = fmaf(x[i].z, w[j].z, acc[i][j]);
                    acc[i][j] = fmaf(x[i].w, w[j].w, acc[i][j]);
                }
        }
        #pragma unroll
        for (int i = 0; i < 4; i++)
            #pragma unroll
            for (int j = 0; j < 3; j++) {
                int r = rg * 4 + i, c = cg + 8 * j;
                if (c < DLL) {
                    float lr = tf32r(acc[i][j]);
                    SL[r * 20 + c] = lr;
                    g_l[side][(size_t)(r0 + r) * DLL + c] = lr;
                } else {
                    STH[r * 12 + (c - 16)] = acc[i][j];
                }
            }
    }
    __syncthreads();

    {
        int r = tid >> 1, half = tid & 1;
        const float* sr = SROW + r * 132 + half * 64;
        float a = 0.f;
        #pragma unroll
        for (int c4 = 0; c4 < 16; c4++) {
            float4 x = *(const float4*)(sr + c4 * 4);
            float x0 = bf16r(x.x), x1 = bf16r(x.y);
            float x2 = bf16r(x.z), x3 = bf16r(x.w);
            a = fmaf(x0, x0, a); a = fmaf(x1, x1, a);
            a = fmaf(x2, x2, a); a = fmaf(x3, x3, a);
        }
        a += __shfl_xor_sync(0xffffffffu, a, 1);
        if (half == 0) g_hn[side][r0 + r] = a;
    }
    if (tid < 64) {
        const float* sr = SL + tid * 20;
        float a = 0.f;
        #pragma unroll
        for (int c4 = 0; c4 < 4; c4++) {
            float4 x = *(const float4*)(sr + c4 * 4);
            a = fmaf(x.x, x.x, a); a = fmaf(x.y, x.y, a);
            a = fmaf(x.z, x.z, a); a = fmaf(x.w, x.w, a);
        }
        g_ln[side][r0 + tid] = a;
    }

    #pragma unroll
    for (int i = 0; i < 16; i++) {
        int idx = tid + i * 128;
        int r = idx >> 5, c = idx & 31;
        float x = (side == 0) ? __ldg(&b1[c]) : 0.f;
        #pragma unroll
        for (int k = 0; k < KK; k++)
            x = fmaf(STH[r * 12 + k], SCW[k * HTH + c], x);
        float w2 = __ldg(&w2_w[c]);
        float x2 = x * x;
        g_PQ[side][(size_t)(r0 + r) * HTH + c] =
            tf32r((side == 0) ? (2.0f * C0g * w2 * x) : x);
        float v = w2 * (fmaf(C1g, x2 * x2, fmaf(C0g, x2, 0.5f * x)));
        #pragma unroll
        for (int o = 16; o > 0; o >>= 1)
            v += __shfl_xor_sync(0xffffffffu, v, o);
        if (c == 0) g_c[side][r0 + r] = v;
    }
}

// ---------------------------------------------------------------------------
// main: 128x128 tile, 512 threads (16 warps); warp = 32 rows x 32 cols
// (4 m-strips x 4 n-quarters). Each b-fragment feeds 2 mmas.
// ---------------------------------------------------------------------------
// float-word offsets in dynamic smem
#define S_HBT 0                        // 128 x 68 u32 (bf16x2 rows)
#define S_HBS (S_HBT + 128*68)
#define S_PT  (S_HBS + 128*68)         // 128 x 36
#define S_QS  (S_PT  + 128*36)
#define S_LT  (S_QS  + 128*36)         // 128 x 20
#define S_LS  (S_LT  + 128*20)
#define S_LUT (S_LS  + 128*20)         // 2048 float2
#define S_SC  (S_LUT + 4096)           // 768
#define MAIN_SMEM ((S_SC + 768) * 4)

__global__ __launch_bounds__(512)
void main_kernel(const float* __restrict__ w2_b, float* __restrict__ out)
{
    extern __shared__ float S[];
    float* sc = S + S_SC;
    // sc: [0]=hn_t [128]=hn_s [256]=ln_t [384]=ln_s [512]=c_t [640]=c_s

    int bz  = blockIdx.z;
    int t0  = blockIdx.y * 128;
    int s0  = blockIdx.x * 128;
    int tid = threadIdx.x;
    int rt  = bz * TT + t0;
    int rs  = bz * TT + s0;

    // ---- cp.async the bf16 h tiles (overlaps with phase A) ----
    {
        unsigned dT = smem_u32(S + S_HBT);
        unsigned dS = smem_u32(S + S_HBS);
        const unsigned* gt = g_hb[0] + (size_t)rt * 64;
        const unsigned* gs = g_hb[1] + (size_t)rs * 64;
        #pragma unroll
        for (int i = 0; i < 4; i++) {
            int idx = tid + i * 512;        // < 2048
            int r = idx >> 4, c = idx & 15;
            unsigned off = (unsigned)(r * 68 + c * 4) * 4u;
            CP_ASYNC16(dT + off, gt + r * 64 + c * 4);
            CP_ASYNC16(dS + off, gs + r * 64 + c * 4);
        }
        asm volatile("cp.async.commit_group;" ::: "memory");
    }

    // ---- stage phase-A tiles ----
    {
        const float4* pt = (const float4*)(g_PQ[0] + (size_t)rt * HTH);
        const float4* qs = (const float4*)(g_PQ[1] + (size_t)rs * HTH);
        #pragma unroll
        for (int i = 0; i < 2; i++) {
            int idx = tid + i * 512;        // < 1024
            int r = idx >> 3, c4 = idx & 7;
            *(float4*)(S + S_PT + r * 36 + c4 * 4) = pt[r * 8 + c4];
            *(float4*)(S + S_QS + r * 36 + c4 * 4) = qs[r * 8 + c4];
        }
        {
            int r = tid >> 2, c4 = tid & 3;
            const float4* lt = (const float4*)(g_l[0] + (size_t)rt * DLL);
            const float4* ls = (const float4*)(g_l[1] + (size_t)rs * DLL);
            *(float4*)(S + S_LT + r * 20 + c4 * 4) = lt[r * 4 + c4];
            *(float4*)(S + S_LS + r * 20 + c4 * 4) = ls[r * 4 + c4];
        }
        const float4* lv = (const float4*)g_lut;
        #pragma unroll
        for (int i = 0; i < 2; i++) {
            int idx = tid + i * 512;        // < 1024
            *(float4*)(S + S_LUT + idx * 4) = lv[idx];
        }
        if (tid < 128) {
            sc[tid]       = g_hn[0][rt + tid];
            sc[128 + tid] = g_hn[1][rs + tid];
            sc[256 + tid] = g_ln[0][rt + tid];
            sc[384 + tid] = g_ln[1][rs + tid];
            sc[512 + tid] = g_c [0][rt + tid];
            sc[640 + tid] = g_c [1][rs + tid];
        }
    }
    float w2b = __ldg(w2_b);
    __syncthreads();

    int wid  = tid >> 5;        // 0..15
    int lane = tid & 31;
    int g    = lane >> 2;       // 0..7
    int q    = lane & 3;        // 0..3
    int m0   = (wid & 3) * 32;  // warp rows [m0, m0+32): two 16-row halves
    int nq   = wid >> 2;        // n-quarter: ntiles [nq*4, nq*4+4)

    // per-thread row scalars for both m-halves (h = 0,1 -> rows m0+16h+g, +8)
    float ctv[2][2], lntv[2][2], hntv[2][2];
    #pragma unroll
    for (int hh = 0; hh < 2; hh++) {
        int rbase = m0 + 16 * hh + g;
        ctv[hh][0]  = sc[512 + rbase]; ctv[hh][1]  = sc[512 + rbase + 8];
        lntv[hh][0] = sc[256 + rbase]; lntv[hh][1] = sc[256 + rbase + 8];
        hntv[hh][0] = sc[rbase];       hntv[hh][1] = sc[rbase + 8];
    }

    // ============ Phase A: theta + l Grams -> tp[4][2][4] ============
    unsigned aT[2][4][4], aL[2][2][4];
    #pragma unroll
    for (int hh = 0; hh < 2; hh++) {
        int rb = m0 + 16 * hh + g;
        #pragma unroll
        for (int ks = 0; ks < 4; ks++) {
            const float* p0 = S + S_PT + rb * 36 + ks * 8 + q;
            const float* p1 = p0 + 8 * 36;
            aT[hh][ks][0] = ldsu(p0);     aT[hh][ks][1] = ldsu(p1);
            aT[hh][ks][2] = ldsu(p0 + 4); aT[hh][ks][3] = ldsu(p1 + 4);
        }
        #pragma unroll
        for (int ks = 0; ks < 2; ks++) {
            const float* p0 = S + S_LT + rb * 20 + ks * 8 + q;
            const float* p1 = p0 + 8 * 20;
            aL[hh][ks][0] = ldsu(p0);     aL[hh][ks][1] = ldsu(p1);
            aL[hh][ks][2] = ldsu(p0 + 4); aL[hh][ks][3] = ldsu(p1 + 4);
        }
    }

    float tp[4][2][4];
    const float2* slut = (const float2*)(S + S_LUT);

    #pragma unroll
    for (int n = 0; n < 4; n++) {
        int n0 = (nq * 4 + n) * 8;
        float dT[2][4] = {{0.f,0.f,0.f,0.f},{0.f,0.f,0.f,0.f}};
        #pragma unroll
        for (int ks = 0; ks < 4; ks++) {
            const float* bp = S + S_QS + (n0 + g) * 36 + ks * 8 + q;
            unsigned b[2] = { ldsu(bp), ldsu(bp + 4) };
            mma8(dT[0], aT[0][ks], b);
            mma8(dT[1], aT[1][ks], b);
        }
        float dL[2][4] = {{0.f,0.f,0.f,0.f},{0.f,0.f,0.f,0.f}};
        #pragma unroll
        for (int ks = 0; ks < 2; ks++) {
            const float* bp = S + S_LS + (n0 + g) * 20 + ks * 8 + q;
            unsigned b[2] = { ldsu(bp), ldsu(bp + 4) };
            mma8(dL[0], aL[0][ks], b);
            mma8(dL[1], aL[1][ks], b);
        }
        int c0 = n0 + 2 * q, c1 = c0 + 1;
        float cs0  = sc[640 + c0], cs1  = sc[640 + c1];
        float lns0 = sc[384 + c0], lns1 = sc[384 + c1];
        #pragma unroll
        for (int hh = 0; hh < 2; hh++) {
            float csv[4]  = { cs0, cs1, cs0, cs1 };
            float lnsv[4] = { lns0, lns1, lns0, lns1 };
            #pragma unroll
            for (int e = 0; e < 4; e++) {
                float a = w2b + ctv[hh][e >> 1] + csv[e] + dT[hh][e];
                float u = a * a;
                float Th = a * fmaf(u, fmaf(u, fmaf(u, -0.05396825397f,
                                     0.13333333333f), -0.33333333333f), 1.0f);
                float dl2 = fmaxf(fmaf(-2.f, dL[hh][e],
                                       lntv[hh][e >> 1] + lnsv[e]), 0.f);
                float t   = fminf(dl2 * LUTSCL, (float)(LUTN - 1));
                int   ix  = (int)t;
                float fr  = t - (float)ix;
                float2 lv = slut[ix];
                tp[n][hh][e] = -Th * fmaf(fr, lv.y, lv.x);
            }
        }
    }

    // ============ Phase B: h Gram (bf16, K=128 -> 8 ksteps) ============
    asm volatile("cp.async.wait_group 0;" ::: "memory");
    __syncthreads();

    const unsigned* HBT = (const unsigned*)(S + S_HBT);
    const unsigned* HBS = (const unsigned*)(S + S_HBS);

    float acc[4][2][4];
    #pragma unroll
    for (int n = 0; n < 4; n++)
        #pragma unroll
        for (int hh = 0; hh < 2; hh++)
            #pragma unroll
            for (int e = 0; e < 4; e++) acc[n][hh][e] = 0.f;

    #pragma unroll 4
    for (int ks = 0; ks < 8; ks++) {
        int kb = ks * 8;
        unsigned a[2][4];
        #pragma unroll
        for (int hh = 0; hh < 2; hh++) {
            const unsigned* pT = HBT + (m0 + 16 * hh + g) * 68 + kb + q;
            a[hh][0] = pT[0]; a[hh][1] = pT[8 * 68];
            a[hh][2] = pT[4]; a[hh][3] = pT[8 * 68 + 4];
        }
        #pragma unroll
        for (int n = 0; n < 4; n++) {
            const unsigned* pS = HBS + ((nq * 4 + n) * 8 + g) * 68 + kb + q;
            unsigned b[2] = { pS[0], pS[4] };
            mma16(acc[n][0], a[0], b);
            mma16(acc[n][1], a[1], b);
        }
    }

    // ============ epilogue ============
    #pragma unroll
    for (int hh = 0; hh < 2; hh++) {
        size_t orow0 = ((size_t)(bz * TT + t0 + m0 + 16 * hh + g)) * TT + s0;
        size_t orow1 = orow0 + (size_t)8 * TT;
        #pragma unroll
        for (int n = 0; n < 4; n++) {
            int c0 = (nq * 4 + n) * 8 + 2 * q;
            float hns0 = sc[128 + c0], hns1 = sc[128 + c0 + 1];
            float d0 = fmaxf(fmaf(-2.f, acc[n][hh][0], hntv[hh][0] + hns0), 0.f) + EPS2;
            float d1 = fmaxf(fmaf(-2.f, acc[n][hh][1], hntv[hh][0] + hns1), 0.f) + EPS2;
            float d2 = fmaxf(fmaf(-2.f, acc[n][hh][2], hntv[hh][1] + hns0), 0.f) + EPS2;
            float d3 = fmaxf(fmaf(-2.f, acc[n][hh][3], hntv[hh][1] + hns1), 0.f) + EPS2;
            float2 v0 = make_float2(tp[n][hh][0] * rsqrtf(d0),
                                    tp[n][hh][1] * rsqrtf(d1));
            float2 v1 = make_float2(tp[n][hh][2] * rsqrtf(d2),
                                    tp[n][hh][3] * rsqrtf(d3));
            *(float2*)(out + orow0 + c0) = v0;
            *(float2*)(out + orow1 + c0) = v1;
        }
    }
}

// ---------------------------------------------------------------------------
extern "C" void kernel_launch(void* const* d_in, const int* in_sizes, int n_in,
                              void* d_out, int out_size)
{
    (void)in_sizes; (void)n_in; (void)out_size;
    const float* h       = (const float*)d_in[0];
    const float* hsrc    = (const float*)d_in[1];
    const float* W_l     = (const float*)d_in[2];
    const float* W_theta = (const float*)d_in[3];
    const float* phi1_w  = (const float*)d_in[4];
    const float* phi1_b  = (const float*)d_in[5];
    const float* phi2_w  = (const float*)d_in[6];
    const float* phi2_b  = (const float*)d_in[7];
    const float* wq      = (const float*)d_in[8];
    const float* ws      = (const float*)d_in[9];
    const float* wd      = (const float*)d_in[10];
    const float* b1      = (const float*)d_in[11];
    const float* w2_w    = (const float*)d_in[12];
    const float* w2_b    = (const float*)d_in[13];
    float* out = (float*)d_out;

    cudaFuncSetAttribute(prep_kernel,
                         cudaFuncAttributeMaxDynamicSharedMemorySize, PREP_SMEM);
    cudaFuncSetAttribute(main_kernel,
                         cudaFuncAttributeMaxDynamicSharedMemorySize, MAIN_SMEM);

    prep_kernel<<<dim3(64, 3), 128, PREP_SMEM>>>(h, hsrc, W_l, W_theta,
                                                 wq, ws, wd, b1, w2_w,
                                                 phi1_w, phi1_b, phi2_w, phi2_b);
    main_kernel<<<dim3(4, 4, BB), 512, MAIN_SMEM>>>(w2_b, out);
}